// round 12
// baseline (speedup 1.0000x reference)
#include <cuda_runtime.h>
#include <cuda_fp16.h>
#include <math.h>
#include <stdint.h>

// Problem constants (fixed by the reference).
#define NN   500000
#define HID  256
#define NC   104
#define NCP  112
#define NG   2048
#define DIN  106
#define GX   128
#define AUXD 2

// Scratch (zero-initialized at load; graph_mlp re-zeroes g_readout after use).
__device__ float  g_readout[NG * NC];
__device__ __align__(16) __half d_WgT[NCP * 512];   // [class][k] fp16, classes 104..111 zero
__device__ __align__(16) __half d_WtT[NCP * 256];

// ---------------------------------------------------------------------------
// GEMM tiling: 512 threads, 16 warps = 8 row-slices x 2 class-halves.
// Warp tile: 16 rows x 56 classes. BM = 128 rows per CTA.
// ---------------------------------------------------------------------------
#define BM 128
#define NTILES 3907                   // ceil(NN / BM)
#define WROWS 16
#define NF 7                          // n-fragments per warp (7*8 = 56 classes)
#define SAST 40                       // A smem row stride (halves): conflict-free
#define ABUF (WROWS * SAST)           // 640 halves / buffer / warp
#define SWGST 520                     // gate weight smem k-stride (halves)
#define SWTST 264
#define SWG_HALVES (NCP * SWGST)      // 58240
#define SWT_HALVES (NCP * SWTST)      // 29568
#define SA_OFF (SWG_HALVES + SWT_HALVES)          // 87808
#define SMEM_HALVES (SA_OFF + 16 * 2 * ABUF)      // 108288
#define SMEM_TOTAL (SMEM_HALVES * 2)              // 216576 bytes

// ---------------------------------------------------------------------------
// PTX helpers
// ---------------------------------------------------------------------------
__device__ __forceinline__ uint32_t s32(const void* p) {
    return (uint32_t)__cvta_generic_to_shared(p);
}
__device__ __forceinline__ void ldsm4(uint32_t* r, uint32_t addr) {
    asm volatile("ldmatrix.sync.aligned.m8n8.x4.shared.b16 {%0,%1,%2,%3}, [%4];"
                 : "=r"(r[0]), "=r"(r[1]), "=r"(r[2]), "=r"(r[3]) : "r"(addr));
}
__device__ __forceinline__ void ldsm2(uint32_t* r, uint32_t addr) {
    asm volatile("ldmatrix.sync.aligned.m8n8.x2.shared.b16 {%0,%1}, [%2];"
                 : "=r"(r[0]), "=r"(r[1]) : "r"(addr));
}
__device__ __forceinline__ void mma16(float* c, const uint32_t* a,
                                      uint32_t b0, uint32_t b1) {
    asm volatile(
        "mma.sync.aligned.m16n8k16.row.col.f32.f16.f16.f32 "
        "{%0,%1,%2,%3}, {%4,%5,%6,%7}, {%8,%9}, {%0,%1,%2,%3};"
        : "+f"(c[0]), "+f"(c[1]), "+f"(c[2]), "+f"(c[3])
        : "r"(a[0]), "r"(a[1]), "r"(a[2]), "r"(a[3]), "r"(b0), "r"(b1));
}

// ---------------------------------------------------------------------------
// Prologue: transpose + convert weights to fp16 [class][k], zero-pad classes.
// ---------------------------------------------------------------------------
__global__ void prep_weights_kernel(const float* __restrict__ Wg,
                                    const float* __restrict__ Wt) {
    int i = blockIdx.x * blockDim.x + threadIdx.x;
    if (i < NCP * 512) {
        int c = i >> 9, k = i & 511;
        d_WgT[i] = __float2half_rn((c < NC) ? Wg[k * NC + c] : 0.0f);
    }
    if (i < NCP * 256) {
        int c = i >> 8, k = i & 255;
        d_WtT[i] = __float2half_rn((c < NC) ? Wt[k * NC + c] : 0.0f);
    }
}

// ---------------------------------------------------------------------------
// Main GEMM: fp16 mma.sync, weights resident in smem, warp-private A tiles.
// 16 warps; each warp: 16 rows x 56 classes. No __syncthreads after staging.
// ---------------------------------------------------------------------------
__global__ void __launch_bounds__(512, 1)
node_gemm_kernel(const float* __restrict__ Xi,
                 const float* __restrict__ Xf,
                 const int*   __restrict__ gid,
                 const float* __restrict__ bgv,
                 const float* __restrict__ btv) {
    extern __shared__ __align__(16) __half smem[];
    __half* sWg = smem;
    __half* sWt = smem + SWG_HALVES;
    const int tid  = threadIdx.x;
    const int wid  = tid >> 5, lane = tid & 31;
    const int g4   = lane >> 2, tig = lane & 3;
    const int wm   = wid & 7;            // row-slice
    const int cb   = (wid >> 3) * 56;    // class base (0 or 56)
    const long m0  = (long)blockIdx.x * BM;

    // ---- stage all weights once (uint4 = 8 halves) ----
    {
        const uint4* sg = (const uint4*)d_WgT;
        for (int i = tid; i < NCP * 512 / 8; i += 512) {
            int c = i >> 6, kq = i & 63;
            *(uint4*)(sWg + c * SWGST + kq * 8) = sg[i];
        }
        const uint4* st = (const uint4*)d_WtT;
        for (int i = tid; i < NCP * 256 / 8; i += 512) {
            int c = i >> 5, kq = i & 31;
            *(uint4*)(sWt + c * SWTST + kq * 8) = st[i];
        }
    }
    __syncthreads();

    const uint32_t sWg32 = s32(sWg);
    const uint32_t sWt32 = s32(sWt);
    __half* sA = smem + SA_OFF + wid * (2 * ABUF);
    const uint32_t sA32 = s32(sA);

    float accg[NF][4], acct[NF][4];
#pragma unroll
    for (int nf = 0; nf < NF; nf++)
#pragma unroll
        for (int j = 0; j < 4; j++) { accg[nf][j] = 0.f; acct[nf][j] = 0.f; }

    // warp-private A staging: lane covers row (lane&15), k-half (lane>>4)
    const int rowl = lane & 15, half = lane >> 4;
    const long grow = m0 + (long)wm * WROWS + rowl;
    const bool valid = (grow < NN);
    const float* xrow_i = Xi + grow * HID + half * 16;
    const float* xrow_f = Xf + grow * HID + half * 16;
    float4 pf[4];

#define LDA(XR, KC) do {                                                     \
        if (valid) {                                                         \
            const float4* p = (const float4*)((XR) + (KC));                  \
            pf[0] = p[0]; pf[1] = p[1]; pf[2] = p[2]; pf[3] = p[3];          \
        } else {                                                             \
            pf[0] = pf[1] = pf[2] = pf[3] = make_float4(0.f, 0.f, 0.f, 0.f);  \
        }                                                                    \
    } while (0)
#define STA(BUF) do {                                                        \
        __half2 h[8];                                                        \
        h[0] = __floats2half2_rn(pf[0].x, pf[0].y);                          \
        h[1] = __floats2half2_rn(pf[0].z, pf[0].w);                          \
        h[2] = __floats2half2_rn(pf[1].x, pf[1].y);                          \
        h[3] = __floats2half2_rn(pf[1].z, pf[1].w);                          \
        h[4] = __floats2half2_rn(pf[2].x, pf[2].y);                          \
        h[5] = __floats2half2_rn(pf[2].z, pf[2].w);                          \
        h[6] = __floats2half2_rn(pf[3].x, pf[3].y);                          \
        h[7] = __floats2half2_rn(pf[3].z, pf[3].w);                          \
        uint4* dst = (uint4*)(sA + (BUF) * ABUF + rowl * SAST + half * 16);  \
        dst[0] = *(uint4*)&h[0];                                             \
        dst[1] = *(uint4*)&h[4];                                             \
    } while (0)

    LDA(xrow_i, 0);
    STA(0);
    __syncwarp();

    // ldmatrix lane-address components (constant per lane)
    const uint32_t a_row  = lane & 15;
    const uint32_t a_koff = (lane >= 16) ? 8u : 0u;
    const uint32_t b_nrow = (lane & 7) + ((lane >= 16) ? 8u : 0u);
    const uint32_t b_koff = ((lane >> 3) & 1u) * 8u;
    const uint32_t b_trow = cb + 48 + (lane & 7);       // x2 tail rows
    const uint32_t b_tkoff = ((lane >> 3) & 1u) * 8u;   // lanes 0-15 used

    for (int i = 0; i < 16; i++) {
        const bool second = (i >= 8);
        // prefetch next chunk (overlaps with compute)
        if (i < 15) {
            const bool nsec = (i + 1 >= 8);
            LDA(nsec ? xrow_f : xrow_i, ((i + 1) & 7) * 32);
        }

        const uint32_t aBase = sA32 + (i & 1) * (ABUF * 2);
        const int kg = i * 32;           // gate k base (0..511)
        const int kt = (i & 7) * 32;     // trans k base (0..255)
#pragma unroll
        for (int blk = 0; blk < 2; blk++) {
            uint32_t a[4];
            ldsm4(a, aBase + (a_row * SAST + blk * 16 + a_koff) * 2);
            // gate: 3 full x4 groups + x2 tail
#pragma unroll
            for (int p = 0; p < 3; p++) {
                uint32_t bgf[4];
                ldsm4(bgf, sWg32 +
                      ((cb + p * 16 + b_nrow) * SWGST + kg + blk * 16 + b_koff) * 2);
                mma16(accg[2 * p],     a, bgf[0], bgf[1]);
                mma16(accg[2 * p + 1], a, bgf[2], bgf[3]);
            }
            {
                uint32_t bgt[2];
                ldsm2(bgt, sWg32 +
                      (b_trow * SWGST + kg + blk * 16 + b_tkoff) * 2);
                mma16(accg[6], a, bgt[0], bgt[1]);
            }
            if (second) {
#pragma unroll
                for (int p = 0; p < 3; p++) {
                    uint32_t btf[4];
                    ldsm4(btf, sWt32 +
                          ((cb + p * 16 + b_nrow) * SWTST + kt + blk * 16 + b_koff) * 2);
                    mma16(acct[2 * p],     a, btf[0], btf[1]);
                    mma16(acct[2 * p + 1], a, btf[2], btf[3]);
                }
                uint32_t btt[2];
                ldsm2(btt, sWt32 +
                      (b_trow * SWTST + kt + blk * 16 + b_tkoff) * 2);
                mma16(acct[6], a, btt[0], btt[1]);
            }
        }
        if (i < 15) STA((i + 1) & 1);
        __syncwarp();
    }

    // ---- epilogue: bias + sigmoid gate ----
    float v[NF][4];
#pragma unroll
    for (int nf = 0; nf < NF; nf++) {
        float bg0 = 0.f, bg1 = 0.f, bt0 = 0.f, bt1 = 0.f;
        int c0 = cb + nf * 8 + tig * 2;
        if (c0 < NC)     { bg0 = __ldg(bgv + c0);     bt0 = __ldg(btv + c0); }
        if (c0 + 1 < NC) { bg1 = __ldg(bgv + c0 + 1); bt1 = __ldg(btv + c0 + 1); }
#pragma unroll
        for (int idx = 0; idx < 4; idx++) {
            float bgb = (idx & 1) ? bg1 : bg0;
            float btb = (idx & 1) ? bt1 : bt0;
            float gl = accg[nf][idx] + bgb;
            float gate = 1.0f / (1.0f + __expf(-gl));
            v[nf][idx] = gate * (acct[nf][idx] + btb);
        }
    }

    // ---- segment scatter (sorted gid fast path) ----
    const long nb = m0 + (long)wm * WROWS;
    const bool tail = (nb + WROWS - 1 >= NN);
    int gf = -1, gl2 = -2;
    if (!tail) {
        if (lane == 0) { gf = gid[nb]; gl2 = gid[nb + WROWS - 1]; }
        gf  = __shfl_sync(0xffffffffu, gf, 0);
        gl2 = __shfl_sync(0xffffffffu, gl2, 0);
    }

    if (!tail && gf == gl2) {
        float* dst = g_readout + (size_t)gf * NC;
#pragma unroll
        for (int nf = 0; nf < NF; nf++)
#pragma unroll
            for (int j = 0; j < 2; j++) {
                float s = v[nf][j] + v[nf][2 + j];        // rows g4, g4+8
                s += __shfl_xor_sync(0xffffffffu, s, 4);
                s += __shfl_xor_sync(0xffffffffu, s, 8);
                s += __shfl_xor_sync(0xffffffffu, s, 16);
                if (g4 == 0) {
                    int c = cb + nf * 8 + tig * 2 + j;
                    if (c < NC) atomicAdd(dst + c, s);
                }
            }
    } else {
#pragma unroll
        for (int rsel = 0; rsel < 2; rsel++) {
            long node = nb + rsel * 8 + g4;
            if (node < NN) {
                float* dst = g_readout + (size_t)gid[node] * NC;
#pragma unroll
                for (int nf = 0; nf < NF; nf++)
#pragma unroll
                    for (int j = 0; j < 2; j++) {
                        int c = cb + nf * 8 + tig * 2 + j;
                        if (c < NC) atomicAdd(dst + c, v[nf][rsel * 2 + j]);
                    }
            }
        }
    }
#undef LDA
#undef STA
}

// ---------------------------------------------------------------------------
// Per-graph BatchNorm (eval) + MLP (106 -> 128 -> 104), 8 graphs/block,
// weights cached in smem, 4-way ILP on the k loops. Re-zeroes g_readout.
// ---------------------------------------------------------------------------
#define TG 8
#define W1_FLOATS (DIN * GX)
#define W2_FLOATS (GX * NC)
#define MLP_SMEM ((W1_FLOATS + W2_FLOATS) * 4)

__global__ __launch_bounds__(GX)
void graph_mlp_kernel(const float* __restrict__ aux,
                      const float* __restrict__ bn_g,
                      const float* __restrict__ bn_b,
                      const float* __restrict__ bn_m,
                      const float* __restrict__ bn_v,
                      const float* __restrict__ W1,
                      const float* __restrict__ b1,
                      const float* __restrict__ W2,
                      const float* __restrict__ b2,
                      float* __restrict__ out) {
    extern __shared__ float wsm[];
    __shared__ float s_norm[DIN];
    __shared__ float s_h[GX];
    float* W1s = wsm;
    float* W2s = wsm + W1_FLOATS;
    const int t = threadIdx.x;

    for (int i = t; i < W1_FLOATS / 4; i += GX)
        ((float4*)W1s)[i] = ((const float4*)W1)[i];
    for (int i = t; i < W2_FLOATS / 4; i += GX)
        ((float4*)W2s)[i] = ((const float4*)W2)[i];

    const float bn_s = (t < DIN) ? rsqrtf(bn_v[t] + 1e-5f) * bn_g[t] : 0.f;
    const float bn_o = (t < DIN) ? bn_b[t] - bn_m[t] * bn_s : 0.f;
    const float b1v  = b1[t];
    const float b2v  = (t < NC) ? b2[t] : 0.f;
    __syncthreads();

    for (int gi = 0; gi < TG; gi++) {
        const int g = blockIdx.x * TG + gi;
        if (t < DIN) {
            float e = (t < NC) ? g_readout[(size_t)g * NC + t]
                               : aux[(size_t)g * AUXD + (t - NC)];
            s_norm[t] = e * bn_s + bn_o;
        }
        if (t < NC) g_readout[(size_t)g * NC + t] = 0.0f;
        __syncthreads();

        float h0 = b1v, h1 = 0.f, h2 = 0.f, h3 = 0.f;
#pragma unroll 4
        for (int k = 0; k < 104; k += 4) {
            h0 = fmaf(s_norm[k],     W1s[(k)     * GX + t], h0);
            h1 = fmaf(s_norm[k + 1], W1s[(k + 1) * GX + t], h1);
            h2 = fmaf(s_norm[k + 2], W1s[(k + 2) * GX + t], h2);
            h3 = fmaf(s_norm[k + 3], W1s[(k + 3) * GX + t], h3);
        }
        h0 = fmaf(s_norm[104], W1s[104 * GX + t], h0);
        h1 = fmaf(s_norm[105], W1s[105 * GX + t], h1);
        s_h[t] = fmaxf((h0 + h1) + (h2 + h3), 0.0f);
        __syncthreads();

        if (t < NC) {
            float o0 = b2v, o1 = 0.f, o2 = 0.f, o3 = 0.f;
#pragma unroll 4
            for (int k = 0; k < GX; k += 4) {
                o0 = fmaf(s_h[k],     W2s[(k)     * NC + t], o0);
                o1 = fmaf(s_h[k + 1], W2s[(k + 1) * NC + t], o1);
                o2 = fmaf(s_h[k + 2], W2s[(k + 2) * NC + t], o2);
                o3 = fmaf(s_h[k + 3], W2s[(k + 3) * NC + t], o3);
            }
            out[(size_t)g * NC + t] = (o0 + o1) + (o2 + o3);
        }
        __syncthreads();
    }
}

// ---------------------------------------------------------------------------
// Launch
// ---------------------------------------------------------------------------
extern "C" void kernel_launch(void* const* d_in, const int* in_sizes, int n_in,
                              void* d_out, int out_size) {
    const float* Xi  = (const float*)d_in[0];
    const float* Xf  = (const float*)d_in[1];
    const float* aux = (const float*)d_in[2];
    const int*   gid = (const int*)d_in[3];
    int w = (n_in >= 17 && in_sizes[4] <= 1) ? 5 : 4;
    const float* Wg   = (const float*)d_in[w + 0];
    const float* bg   = (const float*)d_in[w + 1];
    const float* Wt   = (const float*)d_in[w + 2];
    const float* bt   = (const float*)d_in[w + 3];
    const float* bn_g = (const float*)d_in[w + 4];
    const float* bn_b = (const float*)d_in[w + 5];
    const float* bn_m = (const float*)d_in[w + 6];
    const float* bn_v = (const float*)d_in[w + 7];
    const float* W1   = (const float*)d_in[w + 8];
    const float* b1   = (const float*)d_in[w + 9];
    const float* W2   = (const float*)d_in[w + 10];
    const float* b2   = (const float*)d_in[w + 11];
    float* out = (float*)d_out;

    cudaFuncSetAttribute(node_gemm_kernel,
                         cudaFuncAttributeMaxDynamicSharedMemorySize, SMEM_TOTAL);
    cudaFuncSetAttribute(graph_mlp_kernel,
                         cudaFuncAttributeMaxDynamicSharedMemorySize, MLP_SMEM);

    prep_weights_kernel<<<(NCP * 512 + 255) / 256, 256>>>(Wg, Wt);
    node_gemm_kernel<<<NTILES, 512, SMEM_TOTAL>>>(Xi, Xf, gid, bg, bt);
    graph_mlp_kernel<<<NG / TG, GX, MLP_SMEM>>>(
        aux, bn_g, bn_b, bn_m, bn_v, W1, b1, W2, b2, out);
}

// round 14
// speedup vs baseline: 1.8346x; 1.8346x over previous
#include <cuda_runtime.h>
#include <cuda_fp16.h>
#include <math.h>
#include <stdint.h>

// Problem constants (fixed by the reference).
#define NN   500000
#define HID  256
#define NC   104
#define NCP  112
#define NG   2048
#define DIN  106
#define GX   128
#define AUXD 2

// Scratch (zero-initialized at load; graph_mlp re-zeroes g_readout after use).
__device__ float  g_readout[NG * NC];
__device__ __align__(16) __half d_WgT[NCP * 512];   // [class][k] fp16, classes 104..111 zero
__device__ __align__(16) __half d_WtT[NCP * 256];

// ---------------------------------------------------------------------------
// GEMM tiling (round-10 skeleton: 8 warps = 8 M-slices x 112 N)
// ---------------------------------------------------------------------------
#define BM 128
#define NTILES 3907                   // ceil(NN / BM)
#define WROWS 16
#define SAST 56                       // A smem row stride (halves): conflict-free
#define ABUF (WROWS * SAST)           // 896 halves / buffer / warp
#define SWGST 520                     // gate weight smem k-stride (halves)
#define SWTST 264
#define SWG_HALVES (NCP * SWGST)      // 58240
#define SWT_HALVES (NCP * SWTST)      // 29568
#define SA_OFF (SWG_HALVES + SWT_HALVES)          // 87808
#define SMEM_HALVES (SA_OFF + 8 * 2 * ABUF)       // 102144
#define SMEM_TOTAL (SMEM_HALVES * 2)              // 204288 bytes

// ---------------------------------------------------------------------------
// PTX helpers
// ---------------------------------------------------------------------------
__device__ __forceinline__ uint32_t s32(const void* p) {
    return (uint32_t)__cvta_generic_to_shared(p);
}
__device__ __forceinline__ void ldsm4(uint32_t* r, uint32_t addr) {
    asm volatile("ldmatrix.sync.aligned.m8n8.x4.shared.b16 {%0,%1,%2,%3}, [%4];"
                 : "=r"(r[0]), "=r"(r[1]), "=r"(r[2]), "=r"(r[3]) : "r"(addr));
}
__device__ __forceinline__ void mma16(float* c, const uint32_t* a,
                                      uint32_t b0, uint32_t b1) {
    asm volatile(
        "mma.sync.aligned.m16n8k16.row.col.f32.f16.f16.f32 "
        "{%0,%1,%2,%3}, {%4,%5,%6,%7}, {%8,%9}, {%0,%1,%2,%3};"
        : "+f"(c[0]), "+f"(c[1]), "+f"(c[2]), "+f"(c[3])
        : "r"(a[0]), "r"(a[1]), "r"(a[2]), "r"(a[3]), "r"(b0), "r"(b1));
}

// ---------------------------------------------------------------------------
// Prologue: transpose + convert weights to fp16 [class][k], zero-pad classes.
// ---------------------------------------------------------------------------
__global__ void prep_weights_kernel(const float* __restrict__ Wg,
                                    const float* __restrict__ Wt) {
    int i = blockIdx.x * blockDim.x + threadIdx.x;
    if (i < NCP * 512) {
        int c = i >> 9, k = i & 511;
        d_WgT[i] = __float2half_rn((c < NC) ? Wg[k * NC + c] : 0.0f);
    }
    if (i < NCP * 256) {
        int c = i >> 8, k = i & 255;
        d_WtT[i] = __float2half_rn((c < NC) ? Wt[k * NC + c] : 0.0f);
    }
}

// ---------------------------------------------------------------------------
// Main GEMM: fp16 mma.sync, weights resident in smem, warp-private A tiles,
// 2-chunk LDG lookahead. 8 warps = 8 M-slices x 112 N. No block syncs in loop.
// ---------------------------------------------------------------------------
__global__ void __launch_bounds__(256, 1)
node_gemm_kernel(const float* __restrict__ Xi,
                 const float* __restrict__ Xf,
                 const int*   __restrict__ gid,
                 const float* __restrict__ bgv,
                 const float* __restrict__ btv) {
    extern __shared__ __align__(16) __half smem[];
    __half* sWg = smem;
    __half* sWt = smem + SWG_HALVES;
    const int tid  = threadIdx.x;
    const int wid  = tid >> 5, lane = tid & 31;
    const int g4   = lane >> 2, tig = lane & 3;
    const long m0  = (long)blockIdx.x * BM;

    // ---- stage all weights once (uint4 = 8 halves) ----
    {
        const uint4* sg = (const uint4*)d_WgT;
        for (int i = tid; i < NCP * 512 / 8; i += 256) {
            int c = i >> 6, kq = i & 63;
            *(uint4*)(sWg + c * SWGST + kq * 8) = sg[i];
        }
        const uint4* st = (const uint4*)d_WtT;
        for (int i = tid; i < NCP * 256 / 8; i += 256) {
            int c = i >> 5, kq = i & 31;
            *(uint4*)(sWt + c * SWTST + kq * 8) = st[i];
        }
    }
    __syncthreads();

    const uint32_t sWg32 = s32(sWg);
    const uint32_t sWt32 = s32(sWt);
    __half* sA = smem + SA_OFF + wid * (2 * ABUF);
    const uint32_t sA32 = s32(sA);

    float accg[14][4], acct[14][4];
#pragma unroll
    for (int nf = 0; nf < 14; nf++)
#pragma unroll
        for (int j = 0; j < 4; j++) { accg[nf][j] = 0.f; acct[nf][j] = 0.f; }

    // warp-private A staging: lane covers row (lane&15), k-half (lane>>4)
    const int rowl = lane & 15, half = lane >> 4;
    const long grow = m0 + (long)wid * WROWS + rowl;
    const bool valid = (grow < NN);
    const float* xrow_i = Xi + grow * HID + half * 16;
    const float* xrow_f = Xf + grow * HID + half * 16;
    float4 pf[2][4];     // two lookahead register sets

    // LDA(J, SET): global->reg load of A data for chunk J (0..15).
#define LDA(J, SET) do {                                                     \
        if (valid) {                                                         \
            const float* _b = ((J) >= 8) ? xrow_f : xrow_i;                  \
            const float4* _p = (const float4*)(_b + ((J) & 7) * 32);         \
            pf[SET][0] = _p[0]; pf[SET][1] = _p[1];                          \
            pf[SET][2] = _p[2]; pf[SET][3] = _p[3];                          \
        } else {                                                             \
            pf[SET][0] = pf[SET][1] = pf[SET][2] = pf[SET][3] =              \
                make_float4(0.f, 0.f, 0.f, 0.f);                             \
        }                                                                    \
    } while (0)
#define STA(BUF, SET) do {                                                   \
        __half2 h[8];                                                        \
        h[0] = __floats2half2_rn(pf[SET][0].x, pf[SET][0].y);                \
        h[1] = __floats2half2_rn(pf[SET][0].z, pf[SET][0].w);                \
        h[2] = __floats2half2_rn(pf[SET][1].x, pf[SET][1].y);                \
        h[3] = __floats2half2_rn(pf[SET][1].z, pf[SET][1].w);                \
        h[4] = __floats2half2_rn(pf[SET][2].x, pf[SET][2].y);                \
        h[5] = __floats2half2_rn(pf[SET][2].z, pf[SET][2].w);                \
        h[6] = __floats2half2_rn(pf[SET][3].x, pf[SET][3].y);                \
        h[7] = __floats2half2_rn(pf[SET][3].z, pf[SET][3].w);                \
        uint4* dst = (uint4*)(sA + (BUF) * ABUF + rowl * SAST + half * 16);  \
        dst[0] = *(uint4*)&h[0];                                             \
        dst[1] = *(uint4*)&h[4];                                             \
    } while (0)

    // prologue: chunk 0 staged; chunk 1 in flight in registers
    LDA(0, 0);
    STA(0, 0);
    LDA(1, 1);
    __syncwarp();

    // ldmatrix lane-address components (constant per lane)
    const uint32_t a_row  = lane & 15;
    const uint32_t a_koff = (lane >= 16) ? 8u : 0u;
    const uint32_t b_nrow = (lane & 7) + ((lane >= 16) ? 8u : 0u);
    const uint32_t b_koff = ((lane >> 3) & 1u) * 8u;

#pragma unroll
    for (int i = 0; i < 16; i++) {
        const bool second = (i >= 8);

        // prefetch chunk i+2 into the register set freed by chunk i
        if (i + 2 < 16) LDA(i + 2, i & 1);

        const uint32_t aBase = sA32 + (i & 1) * (ABUF * 2);
        const int kg = i * 32;           // gate k base (0..511)
        const int kt = (i & 7) * 32;     // trans k base (0..255)
#pragma unroll
        for (int blk = 0; blk < 2; blk++) {
            uint32_t a[4];
            ldsm4(a, aBase + (a_row * SAST + blk * 16 + a_koff) * 2);
#pragma unroll
            for (int p = 0; p < 7; p++) {
                uint32_t bgf[4];
                ldsm4(bgf, sWg32 +
                      ((p * 16 + b_nrow) * SWGST + kg + blk * 16 + b_koff) * 2);
                mma16(accg[2 * p],     a, bgf[0], bgf[1]);
                mma16(accg[2 * p + 1], a, bgf[2], bgf[3]);
                if (second) {
                    uint32_t btf[4];
                    ldsm4(btf, sWt32 +
                          ((p * 16 + b_nrow) * SWTST + kt + blk * 16 + b_koff) * 2);
                    mma16(acct[2 * p],     a, btf[0], btf[1]);
                    mma16(acct[2 * p + 1], a, btf[2], btf[3]);
                }
            }
        }
        // stage chunk i+1 (loaded 1 iteration ago) into buffer (i+1)&1
        if (i < 15) STA((i + 1) & 1, (i + 1) & 1);
        __syncwarp();
    }

    // ---- epilogue: bias + sigmoid gate ----
    float v[14][4];
#pragma unroll
    for (int nf = 0; nf < 14; nf++) {
        float bg0 = 0.f, bg1 = 0.f, bt0 = 0.f, bt1 = 0.f;
        int c0 = nf * 8 + tig * 2;
        if (c0 < NC)     { bg0 = __ldg(bgv + c0);     bt0 = __ldg(btv + c0); }
        if (c0 + 1 < NC) { bg1 = __ldg(bgv + c0 + 1); bt1 = __ldg(btv + c0 + 1); }
#pragma unroll
        for (int idx = 0; idx < 4; idx++) {
            float bgb = (idx & 1) ? bg1 : bg0;
            float btb = (idx & 1) ? bt1 : bt0;
            float gl = accg[nf][idx] + bgb;
            float gate = 1.0f / (1.0f + __expf(-gl));
            v[nf][idx] = gate * (acct[nf][idx] + btb);
        }
    }

    // ---- segment scatter (sorted gid fast path) ----
    const long nb = m0 + (long)wid * WROWS;
    const bool tail = (nb + WROWS - 1 >= NN);
    int gf = -1, gl2 = -2;
    if (!tail) {
        if (lane == 0) { gf = gid[nb]; gl2 = gid[nb + WROWS - 1]; }
        gf  = __shfl_sync(0xffffffffu, gf, 0);
        gl2 = __shfl_sync(0xffffffffu, gl2, 0);
    }

    if (!tail && gf == gl2) {
        float* dst = g_readout + (size_t)gf * NC;
#pragma unroll
        for (int nf = 0; nf < 14; nf++)
#pragma unroll
            for (int j = 0; j < 2; j++) {
                float s = v[nf][j] + v[nf][2 + j];        // rows g4, g4+8
                s += __shfl_xor_sync(0xffffffffu, s, 4);
                s += __shfl_xor_sync(0xffffffffu, s, 8);
                s += __shfl_xor_sync(0xffffffffu, s, 16);
                if (g4 == 0) {
                    int c = nf * 8 + tig * 2 + j;
                    if (c < NC) atomicAdd(dst + c, s);
                }
            }
    } else {
#pragma unroll
        for (int rsel = 0; rsel < 2; rsel++) {
            long node = nb + rsel * 8 + g4;
            if (node < NN) {
                float* dst = g_readout + (size_t)gid[node] * NC;
#pragma unroll
                for (int nf = 0; nf < 14; nf++)
#pragma unroll
                    for (int j = 0; j < 2; j++) {
                        int c = nf * 8 + tig * 2 + j;
                        if (c < NC) atomicAdd(dst + c, v[nf][rsel * 2 + j]);
                    }
            }
        }
    }
#undef LDA
#undef STA
}

// ---------------------------------------------------------------------------
// Per-graph BatchNorm (eval) + MLP (106 -> 128 -> 104), 8 graphs/block,
// weights cached in smem, 4-way ILP on the k loops. Re-zeroes g_readout.
// ---------------------------------------------------------------------------
#define TG 8
#define W1_FLOATS (DIN * GX)
#define W2_FLOATS (GX * NC)
#define MLP_SMEM ((W1_FLOATS + W2_FLOATS) * 4)

__global__ __launch_bounds__(GX)
void graph_mlp_kernel(const float* __restrict__ aux,
                      const float* __restrict__ bn_g,
                      const float* __restrict__ bn_b,
                      const float* __restrict__ bn_m,
                      const float* __restrict__ bn_v,
                      const float* __restrict__ W1,
                      const float* __restrict__ b1,
                      const float* __restrict__ W2,
                      const float* __restrict__ b2,
                      float* __restrict__ out) {
    extern __shared__ float wsm[];
    __shared__ float s_norm[DIN];
    __shared__ float s_h[GX];
    float* W1s = wsm;
    float* W2s = wsm + W1_FLOATS;
    const int t = threadIdx.x;

    for (int i = t; i < W1_FLOATS / 4; i += GX)
        ((float4*)W1s)[i] = ((const float4*)W1)[i];
    for (int i = t; i < W2_FLOATS / 4; i += GX)
        ((float4*)W2s)[i] = ((const float4*)W2)[i];

    const float bn_s = (t < DIN) ? rsqrtf(bn_v[t] + 1e-5f) * bn_g[t] : 0.f;
    const float bn_o = (t < DIN) ? bn_b[t] - bn_m[t] * bn_s : 0.f;
    const float b1v  = b1[t];
    const float b2v  = (t < NC) ? b2[t] : 0.f;
    __syncthreads();

    for (int gi = 0; gi < TG; gi++) {
        const int g = blockIdx.x * TG + gi;
        if (t < DIN) {
            float e = (t < NC) ? g_readout[(size_t)g * NC + t]
                               : aux[(size_t)g * AUXD + (t - NC)];
            s_norm[t] = e * bn_s + bn_o;
        }
        if (t < NC) g_readout[(size_t)g * NC + t] = 0.0f;
        __syncthreads();

        float h0 = b1v, h1 = 0.f, h2 = 0.f, h3 = 0.f;
#pragma unroll 4
        for (int k = 0; k < 104; k += 4) {
            h0 = fmaf(s_norm[k],     W1s[(k)     * GX + t], h0);
            h1 = fmaf(s_norm[k + 1], W1s[(k + 1) * GX + t], h1);
            h2 = fmaf(s_norm[k + 2], W1s[(k + 2) * GX + t], h2);
            h3 = fmaf(s_norm[k + 3], W1s[(k + 3) * GX + t], h3);
        }
        h0 = fmaf(s_norm[104], W1s[104 * GX + t], h0);
        h1 = fmaf(s_norm[105], W1s[105 * GX + t], h1);
        s_h[t] = fmaxf((h0 + h1) + (h2 + h3), 0.0f);
        __syncthreads();

        if (t < NC) {
            float o0 = b2v, o1 = 0.f, o2 = 0.f, o3 = 0.f;
#pragma unroll 4
            for (int k = 0; k < GX; k += 4) {
                o0 = fmaf(s_h[k],     W2s[(k)     * NC + t], o0);
                o1 = fmaf(s_h[k + 1], W2s[(k + 1) * NC + t], o1);
                o2 = fmaf(s_h[k + 2], W2s[(k + 2) * NC + t], o2);
                o3 = fmaf(s_h[k + 3], W2s[(k + 3) * NC + t], o3);
            }
            out[(size_t)g * NC + t] = (o0 + o1) + (o2 + o3);
        }
        __syncthreads();
    }
}

// ---------------------------------------------------------------------------
// Launch
// ---------------------------------------------------------------------------
extern "C" void kernel_launch(void* const* d_in, const int* in_sizes, int n_in,
                              void* d_out, int out_size) {
    const float* Xi  = (const float*)d_in[0];
    const float* Xf  = (const float*)d_in[1];
    const float* aux = (const float*)d_in[2];
    const int*   gid = (const int*)d_in[3];
    int w = (n_in >= 17 && in_sizes[4] <= 1) ? 5 : 4;
    const float* Wg   = (const float*)d_in[w + 0];
    const float* bg   = (const float*)d_in[w + 1];
    const float* Wt   = (const float*)d_in[w + 2];
    const float* bt   = (const float*)d_in[w + 3];
    const float* bn_g = (const float*)d_in[w + 4];
    const float* bn_b = (const float*)d_in[w + 5];
    const float* bn_m = (const float*)d_in[w + 6];
    const float* bn_v = (const float*)d_in[w + 7];
    const float* W1   = (const float*)d_in[w + 8];
    const float* b1   = (const float*)d_in[w + 9];
    const float* W2   = (const float*)d_in[w + 10];
    const float* b2   = (const float*)d_in[w + 11];
    float* out = (float*)d_out;

    cudaFuncSetAttribute(node_gemm_kernel,
                         cudaFuncAttributeMaxDynamicSharedMemorySize, SMEM_TOTAL);
    cudaFuncSetAttribute(graph_mlp_kernel,
                         cudaFuncAttributeMaxDynamicSharedMemorySize, MLP_SMEM);

    prep_weights_kernel<<<(NCP * 512 + 255) / 256, 256>>>(Wg, Wt);
    node_gemm_kernel<<<NTILES, 256, SMEM_TOTAL>>>(Xi, Xf, gid, bg, bt);
    graph_mlp_kernel<<<NG / TG, GX, MLP_SMEM>>>(
        aux, bn_g, bn_b, bn_m, bn_v, W1, b1, W2, b2, out);
}